// round 16
// baseline (speedup 1.0000x reference)
#include <cuda_runtime.h>

// AttnPainter: composite the last K strokes (top_k over stroke index; pred =
// 1-alpha_raw > 0 always since alpha_raw ~ U[0,1)) onto a white canvas.
//
// out[b,c,y,x] = fold over n = N-K .. N-1 (increasing):
//     canvas = canvas * a + (1 - a) * colors[b,n,c],  a = alpha[b,n,y,x]
// starting from canvas = 1.
//
// FINAL — converged optimum over 15 measured rounds:
//   - one scalar pixel per thread, full K=10 per thread (no split/shuffles)
//   - 131072 threads = 4096 warps; 128-thread CTAs (1024 blocks) — best of
//     the 128/256/512 block-size curve (5.09/5.18/5.47 us)
//   - MLP 10 front-batched, perfectly coalesced LDG.32s
//   - colors staged in SMEM once per block, colors LDG hoisted ahead of the
//     alpha batch so the barrier drains under the in-flight loads
// Rejected by measurement: float2/float4 widths, K-split + shuffle combine
// (2048/4096/8192-warp variants), __ldcs, pure-FFMA chain rewrite, balanced
// split epilogue. Residual = launch/ramp overhead + 5.2 MB at ~1 TB/s.

constexpr int B = 8;
constexpr int N = 256;
constexpr int W = 128;
constexpr int K = 10;
constexpr int PIX = W * W;           // 16384 pixels per (b, n) slice

__global__ __launch_bounds__(128)
void attn_painter_kernel(const float* __restrict__ alpha,
                         const float* __restrict__ colors,
                         float* __restrict__ out) {
    __shared__ float scol[3 * K];                      // 30 floats

    int tid = blockIdx.x * blockDim.x + threadIdx.x;   // 0 .. B*PIX-1
    int b   = tid >> 14;                               // / PIX (one b per block)
    int p   = tid & (PIX - 1);

    // Issue the colors load FIRST so the barrier below can release while the
    // alpha loads are still in flight.
    float cval = 0.f;
    if (threadIdx.x < 3 * K) {
        cval = __ldg(colors + ((size_t)b * N + (N - K)) * 3 + threadIdx.x);
    }

    // Front-batch the 10 alpha loads (independent, coalesced LDG.32s).
    const float* a_base = alpha + (size_t)b * N * PIX + (size_t)(N - K) * PIX + p;
    float a[K];
#pragma unroll
    for (int k = 0; k < K; k++) {
        a[k] = __ldg(a_base + k * PIX);
    }

    if (threadIdx.x < 3 * K) {
        scol[threadIdx.x] = cval;
    }
    __syncthreads();

    float col[K][3];
#pragma unroll
    for (int k = 0; k < K; k++) {
#pragma unroll
        for (int c = 0; c < 3; c++) {
            col[k][c] = scol[k * 3 + c];
        }
    }

    // Composite all 3 channels in one pass over k (a[k] reused 3x).
    float cv0 = 1.f, cv1 = 1.f, cv2 = 1.f;
#pragma unroll
    for (int k = 0; k < K; k++) {
        float ak = a[k];
        // canvas = canvas*a + (1-a)*col == fma(a, canvas-col, col)
        cv0 = fmaf(ak, cv0 - col[k][0], col[k][0]);
        cv1 = fmaf(ak, cv1 - col[k][1], col[k][1]);
        cv2 = fmaf(ak, cv2 - col[k][2], col[k][2]);
    }

    float* out_base = out + (size_t)b * 3 * PIX + p;
    out_base[0 * PIX] = cv0;
    out_base[1 * PIX] = cv1;
    out_base[2 * PIX] = cv2;
}

extern "C" void kernel_launch(void* const* d_in, const int* in_sizes, int n_in,
                              void* d_out, int out_size) {
    const float* alpha  = (const float*)d_in[0];   // [B, N, W, W] fp32
    const float* colors = (const float*)d_in[1];   // [B, N, 3]    fp32
    float* out = (float*)d_out;                    // [B, 3, W, W] fp32

    int total_threads = B * PIX;                   // 131072
    int block = 128;
    int grid = total_threads / block;              // 1024 blocks
    attn_painter_kernel<<<grid, block>>>(alpha, colors, out);
}

// round 17
// speedup vs baseline: 1.0048x; 1.0048x over previous
#include <cuda_runtime.h>

// AttnPainter: composite the last K strokes (top_k over stroke index; pred =
// 1-alpha_raw > 0 always since alpha_raw ~ U[0,1)) onto a white canvas.
//
// out[b,c,y,x] = fold over n = N-K .. N-1 (increasing):
//     canvas = canvas * a + (1 - a) * colors[b,n,c],  a = alpha[b,n,y,x]
// starting from canvas = 1.
//
// Converged shape: one scalar pixel per thread, full K=10 per thread, 4096
// warps, MLP-10 front-batched coalesced LDG.32s, SMEM colors hoisted.
// R17 probe: 64-thread CTAs (2048 blocks) — next point on the measured
// monotone block-size curve (512:5.47, 256:5.18, 128:5.09 us). Barrier
// scope shrinks to 2 warps.

constexpr int B = 8;
constexpr int N = 256;
constexpr int W = 128;
constexpr int K = 10;
constexpr int PIX = W * W;           // 16384 pixels per (b, n) slice

__global__ __launch_bounds__(64)
void attn_painter_kernel(const float* __restrict__ alpha,
                         const float* __restrict__ colors,
                         float* __restrict__ out) {
    __shared__ float scol[3 * K];                      // 30 floats

    int tid = blockIdx.x * blockDim.x + threadIdx.x;   // 0 .. B*PIX-1
    int b   = tid >> 14;                               // / PIX (one b per block)
    int p   = tid & (PIX - 1);

    // Issue the colors load FIRST so the barrier below can release while the
    // alpha loads are still in flight.
    float cval = 0.f;
    if (threadIdx.x < 3 * K) {
        cval = __ldg(colors + ((size_t)b * N + (N - K)) * 3 + threadIdx.x);
    }

    // Front-batch the 10 alpha loads (independent, coalesced LDG.32s).
    const float* a_base = alpha + (size_t)b * N * PIX + (size_t)(N - K) * PIX + p;
    float a[K];
#pragma unroll
    for (int k = 0; k < K; k++) {
        a[k] = __ldg(a_base + k * PIX);
    }

    if (threadIdx.x < 3 * K) {
        scol[threadIdx.x] = cval;
    }
    __syncthreads();

    float col[K][3];
#pragma unroll
    for (int k = 0; k < K; k++) {
#pragma unroll
        for (int c = 0; c < 3; c++) {
            col[k][c] = scol[k * 3 + c];
        }
    }

    // Composite all 3 channels in one pass over k (a[k] reused 3x).
    float cv0 = 1.f, cv1 = 1.f, cv2 = 1.f;
#pragma unroll
    for (int k = 0; k < K; k++) {
        float ak = a[k];
        // canvas = canvas*a + (1-a)*col == fma(a, canvas-col, col)
        cv0 = fmaf(ak, cv0 - col[k][0], col[k][0]);
        cv1 = fmaf(ak, cv1 - col[k][1], col[k][1]);
        cv2 = fmaf(ak, cv2 - col[k][2], col[k][2]);
    }

    float* out_base = out + (size_t)b * 3 * PIX + p;
    out_base[0 * PIX] = cv0;
    out_base[1 * PIX] = cv1;
    out_base[2 * PIX] = cv2;
}

extern "C" void kernel_launch(void* const* d_in, const int* in_sizes, int n_in,
                              void* d_out, int out_size) {
    const float* alpha  = (const float*)d_in[0];   // [B, N, W, W] fp32
    const float* colors = (const float*)d_in[1];   // [B, N, 3]    fp32
    float* out = (float*)d_out;                    // [B, 3, W, W] fp32

    int total_threads = B * PIX;                   // 131072
    int block = 64;
    int grid = total_threads / block;              // 2048 blocks
    attn_painter_kernel<<<grid, block>>>(alpha, colors, out);
}